// round 7
// baseline (speedup 1.0000x reference)
#include <cuda_runtime.h>

// Problem constants (match reference)
#define B   16
#define LX  2048
#define LR  1024
#define D   768
#define T   (LX + LR + 3)   // 3075
#define C8  (D / 8)         // 96 chunks of 8 floats (32B) per row
#define RPB 4               // rows per CTA (B*T = 49200 divisible by 4)

// Streaming policy on both sides (working set 226MB > 126MB L2, nothing
// retainable across replays): evict-first loads + .cs stores.
// NOTE: store asm deliberately has NO "memory" clobber — with it, the
// compiler may not hoist the second row's load above the first store,
// collapsing per-thread MLP to 1 (the R5/R6 mistake). volatile asm keeps
// ld,ld,st,st program order among themselves.

__device__ __forceinline__ void ldg_stream32(const void* p, float4& a, float4& b) {
    unsigned long long r0, r1, r2, r3;
    asm volatile("ld.global.nc.L2::evict_first.v4.b64 {%0,%1,%2,%3}, [%4];"
                 : "=l"(r0), "=l"(r1), "=l"(r2), "=l"(r3)
                 : "l"(p));
    a.x = __uint_as_float((unsigned)(r0));       a.y = __uint_as_float((unsigned)(r0 >> 32));
    a.z = __uint_as_float((unsigned)(r1));       a.w = __uint_as_float((unsigned)(r1 >> 32));
    b.x = __uint_as_float((unsigned)(r2));       b.y = __uint_as_float((unsigned)(r2 >> 32));
    b.z = __uint_as_float((unsigned)(r3));       b.w = __uint_as_float((unsigned)(r3 >> 32));
}

__device__ __forceinline__ void stg_stream32(void* p, float4 a, float4 b) {
    unsigned long long r0 = (unsigned long long)__float_as_uint(a.x) |
                            ((unsigned long long)__float_as_uint(a.y) << 32);
    unsigned long long r1 = (unsigned long long)__float_as_uint(a.z) |
                            ((unsigned long long)__float_as_uint(a.w) << 32);
    unsigned long long r2 = (unsigned long long)__float_as_uint(b.x) |
                            ((unsigned long long)__float_as_uint(b.y) << 32);
    unsigned long long r3 = (unsigned long long)__float_as_uint(b.z) |
                            ((unsigned long long)__float_as_uint(b.w) << 32);
    asm volatile("st.global.cs.v4.b64 [%0], {%1,%2,%3,%4};"
                 :: "l"(p), "l"(r0), "l"(r1), "l"(r2), "l"(r3));
}

// out[b,t,:] =
//   t == 0                          : CLS
//   1 <= t <= lx[b]                 : X[b, t-1]
//   t == lx[b]+1                    : RING
//   lx[b]+2 <= t < lx[b]+2+lr[b]    : Xr[b, t-lx[b]-2]
//   t == lx[b]+lr[b]+2              : END
//   else                            : 0
__global__ __launch_bounds__(2 * C8) void assemble_kernel(
    const float*  __restrict__ X,
    const float*  __restrict__ Xr,
    const float4* __restrict__ CLS,
    const float4* __restrict__ RING,
    const float4* __restrict__ END,
    const int*    __restrict__ lx,
    const int*    __restrict__ lr,
    float*        __restrict__ out)
{
    // 192 threads = two 96-thread groups (3 warps each, no warp divergence
    // within a row). Each group handles 2 of the CTA's 4 rows; each thread
    // moves one 32B chunk per row. Both loads are issued before any store.
    const int half = threadIdx.x / C8;        // 0 or 1
    const int c    = threadIdx.x - half * C8; // 0..95
    const int row0 = blockIdx.x * RPB;

    float4 va[2], vb[2];

    #pragma unroll
    for (int i = 0; i < 2; i++) {
        const int row = row0 + i * 2 + half;
        const int b   = row / T;               // const-div -> mul/shift
        const int t   = row - b * T;

        const int lxb = __ldg(&lx[b]);
        const int lrb = __ldg(&lr[b]);

        if (t == 0) {
            va[i] = CLS[2 * c]; vb[i] = CLS[2 * c + 1];
        } else if (t <= lxb) {
            ldg_stream32(X + ((long)b * LX + (t - 1)) * D + c * 8, va[i], vb[i]);
        } else if (t == lxb + 1) {
            va[i] = RING[2 * c]; vb[i] = RING[2 * c + 1];
        } else if (t < lxb + 2 + lrb) {
            ldg_stream32(Xr + ((long)b * LR + (t - lxb - 2)) * D + c * 8, va[i], vb[i]);
        } else if (t == lxb + lrb + 2) {
            va[i] = END[2 * c]; vb[i] = END[2 * c + 1];
        } else {
            va[i] = make_float4(0.f, 0.f, 0.f, 0.f);
            vb[i] = va[i];
        }
    }

    #pragma unroll
    for (int i = 0; i < 2; i++) {
        const int row = row0 + i * 2 + half;
        stg_stream32(out + (long)row * D + c * 8, va[i], vb[i]);
    }
}

extern "C" void kernel_launch(void* const* d_in, const int* in_sizes, int n_in,
                              void* d_out, int out_size)
{
    const float*  X    = (const float*)d_in[0];
    const float*  Xr   = (const float*)d_in[1];
    const float4* CLS  = (const float4*)d_in[2];
    const float4* RING = (const float4*)d_in[3];
    const float4* END  = (const float4*)d_in[4];
    const int*    lx   = (const int*)d_in[5];
    const int*    lr   = (const int*)d_in[6];
    float*        out  = (float*)d_out;

    dim3 grid((B * T) / RPB);   // 12300 CTAs
    dim3 block(2 * C8);         // 192 threads
    assemble_kernel<<<grid, block>>>(X, Xr, CLS, RING, END, lx, lr, out);
}